// round 13
// baseline (speedup 1.0000x reference)
#include <cuda_runtime.h>
#include <cuda_fp16.h>
#include <cstdint>

#define BB 8
#define TT 256
#define UU 64
#define ENC_DIM 512
#define PRED_DIM 640
#define JDIM 512
#define VOCAB 1024
#define MROWS (BB * TT * UU)   // 131072

// ---------------------------------------------------------------------------
// Device scratch
// ---------------------------------------------------------------------------
__device__ float g_enc_p[BB * TT * JDIM];            // 4 MB
__device__ float g_pred_p[BB * UU * JDIM];           // 1 MB
__device__ __half g_wt[VOCAB * JDIM];                // 1 MB  (W^T fp16)

// ---------------------------------------------------------------------------
// Helpers
// ---------------------------------------------------------------------------
__device__ __forceinline__ uint32_t smem_u32(const void* p) {
    uint32_t a;
    asm("{ .reg .u64 t; cvta.to.shared.u64 t, %1; cvt.u32.u64 %0, t; }" : "=r"(a) : "l"(p));
    return a;
}
#define CP16(dst, src) \
    asm volatile("cp.async.cg.shared.global [%0], [%1], 16;" :: "r"((uint32_t)(dst)), "l"(src) : "memory")
#define CP_COMMIT() asm volatile("cp.async.commit_group;" ::: "memory")

#define LDSM4(r, addr) \
    asm volatile("ldmatrix.sync.aligned.m8n8.x4.shared.b16 {%0,%1,%2,%3}, [%4];" \
                 : "=r"((r)[0]), "=r"((r)[1]), "=r"((r)[2]), "=r"((r)[3]) : "r"(addr))

#define MMA16816(acc, a, b0, b1) \
    asm volatile("mma.sync.aligned.m16n8k16.row.col.f32.f16.f16.f32 " \
                 "{%0,%1,%2,%3},{%4,%5,%6,%7},{%8,%9},{%0,%1,%2,%3};" \
                 : "+f"((acc)[0]), "+f"((acc)[1]), "+f"((acc)[2]), "+f"((acc)[3]) \
                 : "r"((a)[0]), "r"((a)[1]), "r"((a)[2]), "r"((a)[3]), "r"(b0), "r"(b1))

#define STS128(addr, r0, r1, r2, r3) \
    asm volatile("st.shared.v4.b32 [%0], {%1,%2,%3,%4};" \
                 :: "r"(addr), "r"(r0), "r"(r1), "r"(r2), "r"(r3))

// HW tanh (MUFU.TANH): ~2^-11 accuracy, matches fp16 quantization scale
__device__ __forceinline__ float tanh_hw(float x) {
    float y;
    asm("tanh.approx.f32 %0, %1;" : "=f"(y) : "f"(x));
    return y;
}
__device__ __forceinline__ uint32_t pack2h(__half a, __half b) {
    return (uint32_t)__half_as_ushort(a) | ((uint32_t)__half_as_ushort(b) << 16);
}

// ---------------------------------------------------------------------------
// Projection GEMM (fp32 SIMT): C[M, 512] = A[M, K] @ W[K, 512] + bias
// BM=64, BN=64, 256 threads, 4x4 microtile
// ---------------------------------------------------------------------------
template <int K, int WHICH>
__global__ __launch_bounds__(256) void proj_kernel(
    const float* __restrict__ A, const float* __restrict__ W, const float* __restrict__ bias)
{
    __shared__ float As[16][68];
    __shared__ float Bs[16][68];
    float* __restrict__ C = (WHICH == 0) ? g_enc_p : g_pred_p;
    const int N = JDIM;
    const int tid = threadIdx.x;
    const int ty = tid >> 4, tx = tid & 15;
    const int m0 = blockIdx.y * 64, n0 = blockIdx.x * 64;
    const int lm = tid >> 2, lk = (tid & 3) << 2;
    const int bk = tid >> 4, bn = (tid & 15) << 2;

    float acc[4][4];
#pragma unroll
    for (int i = 0; i < 4; i++)
#pragma unroll
        for (int j = 0; j < 4; j++) acc[i][j] = 0.0f;

    for (int k0 = 0; k0 < K; k0 += 16) {
        float4 a4 = *(const float4*)&A[(m0 + lm) * K + k0 + lk];
        As[lk + 0][lm] = a4.x; As[lk + 1][lm] = a4.y;
        As[lk + 2][lm] = a4.z; As[lk + 3][lm] = a4.w;
        *(float4*)&Bs[bk][bn] = *(const float4*)&W[(k0 + bk) * N + n0 + bn];
        __syncthreads();
#pragma unroll
        for (int k = 0; k < 16; k++) {
            float4 av = *(const float4*)&As[k][ty << 2];
            float4 bv = *(const float4*)&Bs[k][tx << 2];
            float a[4] = {av.x, av.y, av.z, av.w};
            float b[4] = {bv.x, bv.y, bv.z, bv.w};
#pragma unroll
            for (int i = 0; i < 4; i++)
#pragma unroll
                for (int j = 0; j < 4; j++) acc[i][j] = fmaf(a[i], b[j], acc[i][j]);
        }
        __syncthreads();
    }
#pragma unroll
    for (int j = 0; j < 4; j++) {
        float bj = bias[n0 + (tx << 2) + j];
#pragma unroll
        for (int i = 0; i < 4; i++)
            C[(m0 + (ty << 2) + i) * N + n0 + (tx << 2) + j] = acc[i][j] + bj;
    }
}

// ---------------------------------------------------------------------------
// prep_W: Wt[v,k] = fp16(W_joint[k,v])
// ---------------------------------------------------------------------------
__global__ __launch_bounds__(256) void prep_w_kernel(const float* __restrict__ W) {
    int gid = blockIdx.x * 256 + threadIdx.x;       // 0 .. 524287
    int v = gid >> 9, k = gid & 511;
    g_wt[gid] = __float2half_rn(W[k * VOCAB + v]);
}

// ---------------------------------------------------------------------------
// Fused joint GEMM: C = tanh(enc_p (+) pred_p)_fp16 @ Wt_fp16^T + bias
// BM=128, BN=128, BK=64, 256 threads (8 warps 2x4), warp tile 64x32.
// B: 3-stage cp.async pipeline. A: computed in-kernel (LDG fp32 from
// L2-resident enc_p/pred_p + MUFU tanh + STS fp16), double-buffered,
// in TWO 16-element chunks per stage so only 32 staging regs are live.
// acc shrunk to 64 regs (BN=128) so the whole thing fits w/o spills.
// ---------------------------------------------------------------------------
#define BM 128
#define BN 128
#define BK 64
#define NSTG 8                          // 512 / 64
#define NPIPE 3                         // B stages
#define ASTRIDE 144                     // 64 fp16 = 128B data, padded to 144B
#define A_PLANE (BM * ASTRIDE)          // 18432
#define B_PLANE (BN * ASTRIDE)          // 18432
#define OFF_B 0
#define OFF_A (NPIPE * B_PLANE)                            // 55296
#define JOINT_SMEM (NPIPE * B_PLANE + 2 * A_PLANE + 1024)  // 93184

__device__ __forceinline__ void load_b_stage(uint32_t sbase, int k0, int n0, int tid) {
#pragma unroll
    for (int it = 0; it < 4; it++) {
        int c = tid + it * 256;            // 0..1023
        int row = c >> 3, cq = c & 7;
        CP16(sbase + row * ASTRIDE + cq * 16,
             g_wt + (size_t)(n0 + row) * JDIM + k0 + cq * 8);
    }
}

// Load fp32 inputs for one 16-element chunk (8 float4 = 32 regs).
__device__ __forceinline__ void load_a_chunk(float4* e, float4* p, int k0, int chunk,
                                             int bt0, int b, int tid) {
    const int r = tid >> 1, h = tid & 1;
    const int bt = bt0 + (r >> 6), u = r & 63;
    const int ko = k0 + h * 32 + chunk * 16;
    const float4* ep = (const float4*)(g_enc_p + (size_t)bt * JDIM + ko);
    const float4* pp = (const float4*)(g_pred_p + ((size_t)(b * UU + u)) * JDIM + ko);
#pragma unroll
    for (int i = 0; i < 4; i++) e[i] = ep[i];
#pragma unroll
    for (int i = 0; i < 4; i++) p[i] = pp[i];
}

// tanh + pack + STS one 16-element chunk (32 bytes) into buffer abase.
__device__ __forceinline__ void finish_a_chunk(uint32_t abase, const float4* e, const float4* p,
                                               int chunk, int tid) {
    const int r = tid >> 1, h = tid & 1;
    uint32_t o[8];
#pragma unroll
    for (int i = 0; i < 4; i++) {
        __half a0 = __float2half_rn(tanh_hw(e[i].x + p[i].x));
        __half a1 = __float2half_rn(tanh_hw(e[i].y + p[i].y));
        __half a2 = __float2half_rn(tanh_hw(e[i].z + p[i].z));
        __half a3 = __float2half_rn(tanh_hw(e[i].w + p[i].w));
        o[i * 2 + 0] = pack2h(a0, a1);
        o[i * 2 + 1] = pack2h(a2, a3);
    }
    const uint32_t dst = abase + r * ASTRIDE + h * 64 + chunk * 32;
    STS128(dst +  0, o[0], o[1], o[2], o[3]);
    STS128(dst + 16, o[4], o[5], o[6], o[7]);
}

__global__ __launch_bounds__(256, 1) void joint_kernel(
    const float* __restrict__ bias, float* __restrict__ out)
{
    extern __shared__ char dsm[];
    const uint32_t sb = smem_u32(dsm);
    float* sbias = (float*)(dsm + NPIPE * B_PLANE + 2 * A_PLANE);

    const int tid = threadIdx.x;
    const int l   = tid & 31;
    const int w   = tid >> 5;
    const int mw  = w & 1;        // 0..1  -> 64-row slab
    const int nw  = w >> 1;       // 0..3  -> 32-col slab
    const int bid = blockIdx.x;
    const int n0  = (bid & 7) * BN;      // n-major within m
    const int m0  = (bid >> 3) * BM;
    const int bt0 = m0 >> 6;
    const int b   = bt0 >> 8;

    if (tid < BN) sbias[tid] = bias[n0 + tid];

    // B prologue: stages 0,1
    load_b_stage(sb + OFF_B + 0 * B_PLANE, 0 * BK, n0, tid); CP_COMMIT();
    load_b_stage(sb + OFF_B + 1 * B_PLANE, 1 * BK, n0, tid); CP_COMMIT();

    // A prologue: compute stage 0 into abuf 0 (chunked; 32 staging regs)
    {
        float4 e[4], p[4];
        load_a_chunk(e, p, 0, 0, bt0, b, tid);
        finish_a_chunk(sb + OFF_A, e, p, 0, tid);
        load_a_chunk(e, p, 0, 1, bt0, b, tid);
        finish_a_chunk(sb + OFF_A, e, p, 1, tid);
    }

    float acc[4][4][4];
#pragma unroll
    for (int i = 0; i < 4; i++)
#pragma unroll
        for (int j = 0; j < 4; j++)
#pragma unroll
            for (int q = 0; q < 4; q++) acc[i][j][q] = 0.0f;

    const uint32_t a_off = (uint32_t)((mw * 64 + (l & 15)) * ASTRIDE + (l >> 4) * 16);
    const uint32_t b_off = (uint32_t)((nw * 32 + ((l >> 4) << 3) + (l & 7)) * ASTRIDE
                                      + ((l >> 3) & 1) * 16);

    for (int s = 0; s < NSTG; s++) {
        // B(s) resident; A(s) STS visible
        asm volatile("cp.async.wait_group 1;" ::: "memory");
        __syncthreads();

        const uint32_t stgB = sb + OFF_B + (s % NPIPE) * B_PLANE;
        const uint32_t stgA = sb + OFF_A + (s & 1) * A_PLANE;
        const uint32_t nxtA = sb + OFF_A + ((s + 1) & 1) * A_PLANE;
        const bool more = (s + 1 < NSTG);

        uint32_t aa[2][4][4], bb[2][2][4];
        float4 e[4], p[4];

        // ---- LDSM kk-pair 0 (kk = 0,1) ----
#pragma unroll
        for (int kk = 0; kk < 2; kk++) {
#pragma unroll
            for (int mf = 0; mf < 4; mf++)
                LDSM4(aa[kk][mf], stgA + a_off + kk * 32 + mf * 16 * ASTRIDE);
#pragma unroll
            for (int np = 0; np < 2; np++)
                LDSM4(bb[kk][np], stgB + b_off + kk * 32 + np * 16 * ASTRIDE);
        }
        // prefetch B(s+2) in the shadow (uniform commit)
        if (s + 2 < NSTG)
            load_b_stage(sb + OFF_B + ((s + 2) % NPIPE) * B_PLANE, (s + 2) * BK, n0, tid);
        CP_COMMIT();

        // A(s+1) chunk 0 LDGs — land under MMA wall 0
        if (more) load_a_chunk(e, p, (s + 1) * BK, 0, bt0, b, tid);

        // ---- MMA wall 0 ----
#pragma unroll
        for (int kk = 0; kk < 2; kk++)
#pragma unroll
            for (int mf = 0; mf < 4; mf++)
#pragma unroll
                for (int np = 0; np < 2; np++) {
                    MMA16816(acc[mf][np * 2 + 0], aa[kk][mf], bb[kk][np][0], bb[kk][np][1]);
                    MMA16816(acc[mf][np * 2 + 1], aa[kk][mf], bb[kk][np][2], bb[kk][np][3]);
                }

        if (more) finish_a_chunk(nxtA, e, p, 0, tid);

        // ---- LDSM kk-pair 1 (kk = 2,3), registers reused ----
#pragma unroll
        for (int kk = 0; kk < 2; kk++) {
#pragma unroll
            for (int mf = 0; mf < 4; mf++)
                LDSM4(aa[kk][mf], stgA + a_off + 64 + kk * 32 + mf * 16 * ASTRIDE);
#pragma unroll
            for (int np = 0; np < 2; np++)
                LDSM4(bb[kk][np], stgB + b_off + 64 + kk * 32 + np * 16 * ASTRIDE);
        }

        // A(s+1) chunk 1 LDGs — land under MMA wall 1
        if (more) load_a_chunk(e, p, (s + 1) * BK, 1, bt0, b, tid);

        // ---- MMA wall 1 ----
#pragma unroll
        for (int kk = 0; kk < 2; kk++)
#pragma unroll
            for (int mf = 0; mf < 4; mf++)
#pragma unroll
                for (int np = 0; np < 2; np++) {
                    MMA16816(acc[mf][np * 2 + 0], aa[kk][mf], bb[kk][np][0], bb[kk][np][1]);
                    MMA16816(acc[mf][np * 2 + 1], aa[kk][mf], bb[kk][np][2], bb[kk][np][3]);
                }

        if (more) finish_a_chunk(nxtA, e, p, 1, tid);
    }

    // epilogue: add bias, direct stores
#pragma unroll
    for (int mf = 0; mf < 4; mf++) {
        const int r0 = m0 + mw * 64 + mf * 16 + (l >> 2);
#pragma unroll
        for (int nf = 0; nf < 4; nf++) {
            const int c  = n0 + nw * 32 + nf * 8 + ((l & 3) << 1);
            const float2 b2 = *(const float2*)&sbias[c - n0];
            float2 o0, o1;
            o0.x = acc[mf][nf][0] + b2.x;
            o0.y = acc[mf][nf][1] + b2.y;
            o1.x = acc[mf][nf][2] + b2.x;
            o1.y = acc[mf][nf][3] + b2.y;
            *(float2*)&out[(size_t)r0 * VOCAB + c]       = o0;
            *(float2*)&out[(size_t)(r0 + 8) * VOCAB + c] = o1;
        }
    }
}

// ---------------------------------------------------------------------------
extern "C" void kernel_launch(void* const* d_in, const int* in_sizes, int n_in,
                              void* d_out, int out_size)
{
    const float* enc_out  = (const float*)d_in[0];
    const float* pred_out = (const float*)d_in[1];
    const float* W_enc    = (const float*)d_in[2];
    const float* b_enc    = (const float*)d_in[3];
    const float* W_pred   = (const float*)d_in[4];
    const float* b_pred   = (const float*)d_in[5];
    const float* W_joint  = (const float*)d_in[6];
    const float* b_joint  = (const float*)d_in[7];
    float* out = (float*)d_out;

    static bool attr_done = false;
    if (!attr_done) {
        cudaFuncSetAttribute(joint_kernel, cudaFuncAttributeMaxDynamicSharedMemorySize, JOINT_SMEM);
        attr_done = true;
    }

    {
        dim3 grid(JDIM / 64, (BB * TT) / 64);   // 256 blocks
        proj_kernel<ENC_DIM, 0><<<grid, 256>>>(enc_out, W_enc, b_enc);
    }
    {
        dim3 grid(JDIM / 64, (BB * UU) / 64);   // 64 blocks
        proj_kernel<PRED_DIM, 1><<<grid, 256>>>(pred_out, W_pred, b_pred);
    }
    prep_w_kernel<<<(VOCAB * JDIM) / 256, 256>>>(W_joint);
    // fused joint: 1024 m-tiles x 8 n-tiles, n-major within m
    joint_kernel<<<(MROWS / BM) * (VOCAB / BN), 256, JOINT_SMEM>>>(b_joint, out);
}

// round 14
// speedup vs baseline: 2.1010x; 2.1010x over previous
#include <cuda_runtime.h>
#include <cuda_fp16.h>
#include <cstdint>

#define BB 8
#define TT 256
#define UU 64
#define ENC_DIM 512
#define PRED_DIM 640
#define JDIM 512
#define VOCAB 1024
#define MROWS (BB * TT * UU)   // 131072

// ---------------------------------------------------------------------------
// Device scratch
// ---------------------------------------------------------------------------
__device__ float g_enc_p[BB * TT * JDIM];            // 4 MB
__device__ float g_pred_p[BB * UU * JDIM];           // 1 MB
__device__ __half g_a[(size_t)MROWS * JDIM];         // 128 MB (fp16 tanh plane)
__device__ __half g_wt[VOCAB * JDIM];                // 1 MB  (W^T fp16)

// ---------------------------------------------------------------------------
// Helpers
// ---------------------------------------------------------------------------
__device__ __forceinline__ uint32_t smem_u32(const void* p) {
    uint32_t a;
    asm("{ .reg .u64 t; cvta.to.shared.u64 t, %1; cvt.u32.u64 %0, t; }" : "=r"(a) : "l"(p));
    return a;
}
#define CP16(dst, src) \
    asm volatile("cp.async.cg.shared.global [%0], [%1], 16;" :: "r"((uint32_t)(dst)), "l"(src) : "memory")
#define CP_COMMIT() asm volatile("cp.async.commit_group;" ::: "memory")

#define LDSM4(r, addr) \
    asm volatile("ldmatrix.sync.aligned.m8n8.x4.shared.b16 {%0,%1,%2,%3}, [%4];" \
                 : "=r"((r)[0]), "=r"((r)[1]), "=r"((r)[2]), "=r"((r)[3]) : "r"(addr))

#define MMA16816(acc, a, b0, b1) \
    asm volatile("mma.sync.aligned.m16n8k16.row.col.f32.f16.f16.f32 " \
                 "{%0,%1,%2,%3},{%4,%5,%6,%7},{%8,%9},{%0,%1,%2,%3};" \
                 : "+f"((acc)[0]), "+f"((acc)[1]), "+f"((acc)[2]), "+f"((acc)[3]) \
                 : "r"((a)[0]), "r"((a)[1]), "r"((a)[2]), "r"((a)[3]), "r"(b0), "r"(b1))

// HW tanh (MUFU.TANH): ~2^-11 accuracy, matches fp16 quantization scale
__device__ __forceinline__ float tanh_hw(float x) {
    float y;
    asm("tanh.approx.f32 %0, %1;" : "=f"(y) : "f"(x));
    return y;
}
__device__ __forceinline__ uint32_t pack2h(__half a, __half b) {
    return (uint32_t)__half_as_ushort(a) | ((uint32_t)__half_as_ushort(b) << 16);
}

// ---------------------------------------------------------------------------
// Projection GEMM (fp32 SIMT): C[M, 512] = A[M, K] @ W[K, 512] + bias
// BM=64, BN=64, 256 threads, 4x4 microtile
// ---------------------------------------------------------------------------
template <int K, int WHICH>
__global__ __launch_bounds__(256) void proj_kernel(
    const float* __restrict__ A, const float* __restrict__ W, const float* __restrict__ bias)
{
    __shared__ float As[16][68];
    __shared__ float Bs[16][68];
    float* __restrict__ C = (WHICH == 0) ? g_enc_p : g_pred_p;
    const int N = JDIM;
    const int tid = threadIdx.x;
    const int ty = tid >> 4, tx = tid & 15;
    const int m0 = blockIdx.y * 64, n0 = blockIdx.x * 64;
    const int lm = tid >> 2, lk = (tid & 3) << 2;
    const int bk = tid >> 4, bn = (tid & 15) << 2;

    float acc[4][4];
#pragma unroll
    for (int i = 0; i < 4; i++)
#pragma unroll
        for (int j = 0; j < 4; j++) acc[i][j] = 0.0f;

    for (int k0 = 0; k0 < K; k0 += 16) {
        float4 a4 = *(const float4*)&A[(m0 + lm) * K + k0 + lk];
        As[lk + 0][lm] = a4.x; As[lk + 1][lm] = a4.y;
        As[lk + 2][lm] = a4.z; As[lk + 3][lm] = a4.w;
        *(float4*)&Bs[bk][bn] = *(const float4*)&W[(k0 + bk) * N + n0 + bn];
        __syncthreads();
#pragma unroll
        for (int k = 0; k < 16; k++) {
            float4 av = *(const float4*)&As[k][ty << 2];
            float4 bv = *(const float4*)&Bs[k][tx << 2];
            float a[4] = {av.x, av.y, av.z, av.w};
            float b[4] = {bv.x, bv.y, bv.z, bv.w};
#pragma unroll
            for (int i = 0; i < 4; i++)
#pragma unroll
                for (int j = 0; j < 4; j++) acc[i][j] = fmaf(a[i], b[j], acc[i][j]);
        }
        __syncthreads();
    }
#pragma unroll
    for (int j = 0; j < 4; j++) {
        float bj = bias[n0 + (tx << 2) + j];
#pragma unroll
        for (int i = 0; i < 4; i++)
            C[(m0 + (ty << 2) + i) * N + n0 + (tx << 2) + j] = acc[i][j] + bj;
    }
}

// ---------------------------------------------------------------------------
// prep_W: Wt[v,k] = fp16(W_joint[k,v])
// ---------------------------------------------------------------------------
__global__ __launch_bounds__(256) void prep_w_kernel(const float* __restrict__ W) {
    int gid = blockIdx.x * 256 + threadIdx.x;       // 0 .. 524287
    int v = gid >> 9, k = gid & 511;
    g_wt[gid] = __float2half_rn(W[k * VOCAB + v]);
}

// ---------------------------------------------------------------------------
// prep_A v2: A[m,k] = fp16(tanh(enc_p[bt,k] + pred_p[b,u,k]))
// One block per bt. Each thread owns one enc float4 (held in registers) and
// streams 32 pred rows (unroll 4 -> 4 LDGs in flight). pred is L2-resident
// (1 MB, 256x reuse); all loads/stores fully coalesced.
// ---------------------------------------------------------------------------
__global__ __launch_bounds__(256) void prep_a_kernel() {
    const int bt  = blockIdx.x;          // 0..2047
    const int b   = bt >> 8;
    const int tid = threadIdx.x;
    const int kq  = tid & 127;           // float4 index within a 512-row
    const int u0  = tid >> 7;            // 0..1

    const float4 e = *((const float4*)(g_enc_p + (size_t)bt * JDIM) + kq);
    const float4* predb = (const float4*)(g_pred_p + (size_t)b * UU * JDIM) + kq;
    uint2* outb = (uint2*)(g_a + (size_t)bt * UU * JDIM) + kq;

#pragma unroll 4
    for (int it = 0; it < 32; it++) {
        const int u = u0 + it * 2;
        float4 p = predb[u * 128];       // row stride = 512 floats = 128 float4
        __half h0 = __float2half_rn(tanh_hw(e.x + p.x));
        __half h1 = __float2half_rn(tanh_hw(e.y + p.y));
        __half h2 = __float2half_rn(tanh_hw(e.z + p.z));
        __half h3 = __float2half_rn(tanh_hw(e.w + p.w));
        uint2 o;
        o.x = pack2h(h0, h1);
        o.y = pack2h(h2, h3);
        outb[u * 128] = o;               // row stride = 512 halfs = 128 uint2
    }
}

// ---------------------------------------------------------------------------
// Joint GEMM via mma.sync (HMMA): C = A_fp16 @ Wt_fp16^T + bias  (single pass)
// BM=128, BN=128, BK=64, 256 threads (8 warps 2x4), warp tile 64x32.
// NPIPE=3 cp.async pipeline, 111.6 KB smem -> 2 blocks/SM.
// ---------------------------------------------------------------------------
#define BM 128
#define BN 128
#define BK 64
#define NSTG 8                          // 512 / 64
#define NPIPE 3
#define ASTRIDE 144                     // 64 fp16 = 128B data, padded to 144B
#define A_PLANE (BM * ASTRIDE)          // 18432
#define B_PLANE (BN * ASTRIDE)          // 18432
#define STG_BYTES (A_PLANE + B_PLANE)   // 36864
#define OFF_A 0
#define OFF_B A_PLANE
#define JOINT_SMEM (NPIPE * STG_BYTES + 1024)  // 111616 (+bias)

__device__ __forceinline__ void load_stage(uint32_t sbase, int k0, int m0, int n0, int tid) {
#pragma unroll
    for (int it = 0; it < 4; it++) {
        int c = tid + it * 256;            // 0..1023
        int row = c >> 3, cq = c & 7;
        CP16(sbase + OFF_A + row * ASTRIDE + cq * 16,
             g_a + (size_t)(m0 + row) * JDIM + k0 + cq * 8);
    }
#pragma unroll
    for (int it = 0; it < 4; it++) {
        int c = tid + it * 256;            // 0..1023
        int row = c >> 3, cq = c & 7;
        CP16(sbase + OFF_B + row * ASTRIDE + cq * 16,
             g_wt + (size_t)(n0 + row) * JDIM + k0 + cq * 8);
    }
}

__global__ __launch_bounds__(256, 2) void joint_kernel(
    const float* __restrict__ bias, float* __restrict__ out)
{
    extern __shared__ char dsm[];
    const uint32_t sb = smem_u32(dsm);
    float* sbias = (float*)(dsm + NPIPE * STG_BYTES);

    const int tid = threadIdx.x;
    const int l   = tid & 31;
    const int w   = tid >> 5;
    const int mw  = w & 1;        // 0..1  -> 64-row slab
    const int nw  = w >> 1;       // 0..3  -> 32-col slab
    const int bid = blockIdx.x;
    const int n0  = (bid & 7) * BN;     // n-major within m: co-resident N-blocks share A via L2
    const int m0  = (bid >> 3) * BM;

    if (tid < BN) sbias[tid] = bias[n0 + tid];

    load_stage(sb + 0 * STG_BYTES, 0 * BK, m0, n0, tid); CP_COMMIT();
    load_stage(sb + 1 * STG_BYTES, 1 * BK, m0, n0, tid); CP_COMMIT();

    float acc[4][4][4];
#pragma unroll
    for (int i = 0; i < 4; i++)
#pragma unroll
        for (int j = 0; j < 4; j++)
#pragma unroll
            for (int q = 0; q < 4; q++) acc[i][j][q] = 0.0f;

    const uint32_t a_off = (uint32_t)((mw * 64 + (l & 15)) * ASTRIDE + (l >> 4) * 16);
    const uint32_t b_off = (uint32_t)((nw * 32 + ((l >> 4) << 3) + (l & 7)) * ASTRIDE
                                      + ((l >> 3) & 1) * 16);

    for (int s = 0; s < NSTG; s++) {
        asm volatile("cp.async.wait_group 1;" ::: "memory");
        __syncthreads();

        const uint32_t stg = sb + (s % NPIPE) * STG_BYTES;
        uint32_t aa[2][4][4], bb[2][2][4];

        // ---- kk-pair 0 (kk = 0,1) ----
#pragma unroll
        for (int kk = 0; kk < 2; kk++) {
#pragma unroll
            for (int mf = 0; mf < 4; mf++)
                LDSM4(aa[kk][mf], stg + OFF_A + a_off + kk * 32 + mf * 16 * ASTRIDE);
#pragma unroll
            for (int np = 0; np < 2; np++)
                LDSM4(bb[kk][np], stg + OFF_B + b_off + kk * 32 + np * 16 * ASTRIDE);
        }
        // prefetch stage s+2 in the shadow (uniform commit)
        if (s + 2 < NSTG)
            load_stage(sb + ((s + 2) % NPIPE) * STG_BYTES, (s + 2) * BK, m0, n0, tid);
        CP_COMMIT();
#pragma unroll
        for (int kk = 0; kk < 2; kk++)
#pragma unroll
            for (int mf = 0; mf < 4; mf++)
#pragma unroll
                for (int np = 0; np < 2; np++) {
                    MMA16816(acc[mf][np * 2 + 0], aa[kk][mf], bb[kk][np][0], bb[kk][np][1]);
                    MMA16816(acc[mf][np * 2 + 1], aa[kk][mf], bb[kk][np][2], bb[kk][np][3]);
                }

        // ---- kk-pair 1 (kk = 2,3), registers reused ----
#pragma unroll
        for (int kk = 0; kk < 2; kk++) {
#pragma unroll
            for (int mf = 0; mf < 4; mf++)
                LDSM4(aa[kk][mf], stg + OFF_A + a_off + 64 + kk * 32 + mf * 16 * ASTRIDE);
#pragma unroll
            for (int np = 0; np < 2; np++)
                LDSM4(bb[kk][np], stg + OFF_B + b_off + 64 + kk * 32 + np * 16 * ASTRIDE);
        }
#pragma unroll
        for (int kk = 0; kk < 2; kk++)
#pragma unroll
            for (int mf = 0; mf < 4; mf++)
#pragma unroll
                for (int np = 0; np < 2; np++) {
                    MMA16816(acc[mf][np * 2 + 0], aa[kk][mf], bb[kk][np][0], bb[kk][np][1]);
                    MMA16816(acc[mf][np * 2 + 1], aa[kk][mf], bb[kk][np][2], bb[kk][np][3]);
                }
    }

    // epilogue: add bias, direct stores
#pragma unroll
    for (int mf = 0; mf < 4; mf++) {
        const int r0 = m0 + mw * 64 + mf * 16 + (l >> 2);
#pragma unroll
        for (int nf = 0; nf < 4; nf++) {
            const int c  = n0 + nw * 32 + nf * 8 + ((l & 3) << 1);
            const float2 b2 = *(const float2*)&sbias[c - n0];
            float2 o0, o1;
            o0.x = acc[mf][nf][0] + b2.x;
            o0.y = acc[mf][nf][1] + b2.y;
            o1.x = acc[mf][nf][2] + b2.x;
            o1.y = acc[mf][nf][3] + b2.y;
            *(float2*)&out[(size_t)r0 * VOCAB + c]       = o0;
            *(float2*)&out[(size_t)(r0 + 8) * VOCAB + c] = o1;
        }
    }
}

// ---------------------------------------------------------------------------
extern "C" void kernel_launch(void* const* d_in, const int* in_sizes, int n_in,
                              void* d_out, int out_size)
{
    const float* enc_out  = (const float*)d_in[0];
    const float* pred_out = (const float*)d_in[1];
    const float* W_enc    = (const float*)d_in[2];
    const float* b_enc    = (const float*)d_in[3];
    const float* W_pred   = (const float*)d_in[4];
    const float* b_pred   = (const float*)d_in[5];
    const float* W_joint  = (const float*)d_in[6];
    const float* b_joint  = (const float*)d_in[7];
    float* out = (float*)d_out;

    static bool attr_done = false;
    if (!attr_done) {
        cudaFuncSetAttribute(joint_kernel, cudaFuncAttributeMaxDynamicSharedMemorySize, JOINT_SMEM);
        attr_done = true;
    }

    {
        dim3 grid(JDIM / 64, (BB * TT) / 64);   // 256 blocks
        proj_kernel<ENC_DIM, 0><<<grid, 256>>>(enc_out, W_enc, b_enc);
    }
    {
        dim3 grid(JDIM / 64, (BB * UU) / 64);   // 64 blocks
        proj_kernel<PRED_DIM, 1><<<grid, 256>>>(pred_out, W_pred, b_pred);
    }
    prep_w_kernel<<<(VOCAB * JDIM) / 256, 256>>>(W_joint);
    prep_a_kernel<<<BB * TT, 256>>>();
    // 1024 m-tiles x 8 n-tiles, n-major within m
    joint_kernel<<<(MROWS / BM) * (VOCAB / BN), 256, JOINT_SMEM>>>(b_joint, out);
}

// round 15
// speedup vs baseline: 2.1908x; 1.0427x over previous
#include <cuda_runtime.h>
#include <cuda_fp16.h>
#include <cstdint>

#define BB 8
#define TT 256
#define UU 64
#define ENC_DIM 512
#define PRED_DIM 640
#define JDIM 512
#define VOCAB 1024
#define MROWS (BB * TT * UU)   // 131072

// ---------------------------------------------------------------------------
// Device scratch
// ---------------------------------------------------------------------------
__device__ float g_enc_p[BB * TT * JDIM];            // 4 MB
__device__ float g_pred_p[BB * UU * JDIM];           // 1 MB
__device__ __half g_a[(size_t)MROWS * JDIM];         // 128 MB (fp16 tanh plane)
__device__ __half g_wt[VOCAB * JDIM];                // 1 MB  (W^T fp16)

// ---------------------------------------------------------------------------
// Helpers
// ---------------------------------------------------------------------------
__device__ __forceinline__ uint32_t smem_u32(const void* p) {
    uint32_t a;
    asm("{ .reg .u64 t; cvta.to.shared.u64 t, %1; cvt.u32.u64 %0, t; }" : "=r"(a) : "l"(p));
    return a;
}
#define CP16(dst, src) \
    asm volatile("cp.async.cg.shared.global [%0], [%1], 16;" :: "r"((uint32_t)(dst)), "l"(src) : "memory")
#define CP_COMMIT() asm volatile("cp.async.commit_group;" ::: "memory")

#define LDSM4(r, addr) \
    asm volatile("ldmatrix.sync.aligned.m8n8.x4.shared.b16 {%0,%1,%2,%3}, [%4];" \
                 : "=r"((r)[0]), "=r"((r)[1]), "=r"((r)[2]), "=r"((r)[3]) : "r"(addr))

#define MMA16816(acc, a, b0, b1) \
    asm volatile("mma.sync.aligned.m16n8k16.row.col.f32.f16.f16.f32 " \
                 "{%0,%1,%2,%3},{%4,%5,%6,%7},{%8,%9},{%0,%1,%2,%3};" \
                 : "+f"((acc)[0]), "+f"((acc)[1]), "+f"((acc)[2]), "+f"((acc)[3]) \
                 : "r"((a)[0]), "r"((a)[1]), "r"((a)[2]), "r"((a)[3]), "r"(b0), "r"(b1))

// HW tanh (MUFU.TANH): ~2^-11 accuracy, matches fp16 quantization scale
__device__ __forceinline__ float tanh_hw(float x) {
    float y;
    asm("tanh.approx.f32 %0, %1;" : "=f"(y) : "f"(x));
    return y;
}
__device__ __forceinline__ uint32_t pack2h(__half a, __half b) {
    return (uint32_t)__half_as_ushort(a) | ((uint32_t)__half_as_ushort(b) << 16);
}

// ---------------------------------------------------------------------------
// Projection GEMM body (fp32 SIMT): C[M, 512] = A[M, K] @ W[K, 512] + bias
// BM=64, BN=64, 256 threads, 4x4 microtile. K is runtime (inner 16 static).
// ---------------------------------------------------------------------------
__device__ __forceinline__ void proj_body(
    float (*As)[68], float (*Bs)[68],
    const float* __restrict__ A, const float* __restrict__ W,
    const float* __restrict__ bias, float* __restrict__ C,
    int K, int bx, int by, int tid)
{
    const int N = JDIM;
    const int ty = tid >> 4, tx = tid & 15;
    const int m0 = by * 64, n0 = bx * 64;
    const int lm = tid >> 2, lk = (tid & 3) << 2;
    const int bk = tid >> 4, bn = (tid & 15) << 2;

    float acc[4][4];
#pragma unroll
    for (int i = 0; i < 4; i++)
#pragma unroll
        for (int j = 0; j < 4; j++) acc[i][j] = 0.0f;

    for (int k0 = 0; k0 < K; k0 += 16) {
        float4 a4 = *(const float4*)&A[(m0 + lm) * K + k0 + lk];
        As[lk + 0][lm] = a4.x; As[lk + 1][lm] = a4.y;
        As[lk + 2][lm] = a4.z; As[lk + 3][lm] = a4.w;
        *(float4*)&Bs[bk][bn] = *(const float4*)&W[(k0 + bk) * N + n0 + bn];
        __syncthreads();
#pragma unroll
        for (int k = 0; k < 16; k++) {
            float4 av = *(const float4*)&As[k][ty << 2];
            float4 bv = *(const float4*)&Bs[k][tx << 2];
            float a[4] = {av.x, av.y, av.z, av.w};
            float b[4] = {bv.x, bv.y, bv.z, bv.w};
#pragma unroll
            for (int i = 0; i < 4; i++)
#pragma unroll
                for (int j = 0; j < 4; j++) acc[i][j] = fmaf(a[i], b[j], acc[i][j]);
        }
        __syncthreads();
    }
#pragma unroll
    for (int j = 0; j < 4; j++) {
        float bj = bias[n0 + (tx << 2) + j];
#pragma unroll
        for (int i = 0; i < 4; i++)
            C[(m0 + (ty << 2) + i) * N + n0 + (tx << 2) + j] = acc[i][j] + bj;
    }
}

// ---------------------------------------------------------------------------
// Merged pre-kernel: one launch runs all three independent preps concurrently.
//   blocks [0, 256):   enc projection  (8 n-tiles x 32 m-tiles)
//   blocks [256, 320): pred projection (8 n-tiles x 8 m-tiles)
//   blocks [320, 328): W transpose + fp16
// ---------------------------------------------------------------------------
__global__ __launch_bounds__(256) void prep_kernel(
    const float* __restrict__ enc_out, const float* __restrict__ W_enc,
    const float* __restrict__ b_enc,
    const float* __restrict__ pred_out, const float* __restrict__ W_pred,
    const float* __restrict__ b_pred,
    const float* __restrict__ W_joint)
{
    __shared__ float As[16][68];
    __shared__ float Bs[16][68];
    const int bid = blockIdx.x;
    const int tid = threadIdx.x;

    if (bid < 256) {
        proj_body(As, Bs, enc_out, W_enc, b_enc, g_enc_p, ENC_DIM,
                  bid & 7, bid >> 3, tid);
    } else if (bid < 320) {
        const int q = bid - 256;
        proj_body(As, Bs, pred_out, W_pred, b_pred, g_pred_p, PRED_DIM,
                  q & 7, q >> 3, tid);
    } else {
        const int q = bid - 320;             // 0..7
#pragma unroll 4
        for (int i = 0; i < 256; i++) {
            int gid = q * 65536 + i * 256 + tid;   // 0 .. 524287
            int v = gid >> 9, k = gid & 511;
            g_wt[gid] = __float2half_rn(W_joint[k * VOCAB + v]);
        }
    }
}

// ---------------------------------------------------------------------------
// prep_A v3: A[m,k] = fp16(tanh(enc_p[bt,k] + pred_p[b,u,k]))
// Flat mapping (R9 style), 4 u-rows per thread (u, u+16, u+32, u+48):
// 10 independent LDG.128 issued up front (enc pair shared by all 4 rows),
// then 32 MUFU tanh, 4 x 16B stores. All accesses fully coalesced.
// ---------------------------------------------------------------------------
__global__ __launch_bounds__(256) void prep_a_kernel() {
    int gid = blockIdx.x * 256 + threadIdx.x;   // 0 .. 2097151
    int bt = gid >> 10;                 // 1024 threads per bt
    int r  = gid & 1023;
    int u  = r >> 6;                    // 0..15
    int k8 = (r & 63) << 3;
    int b  = bt >> 8;

    const float4* e = (const float4*)(g_enc_p + (size_t)bt * JDIM + k8);
    const float4 e0 = e[0], e1 = e[1];

    float4 p[4][2];
    const float4* pb = (const float4*)(g_pred_p + ((size_t)(b * UU)) * JDIM + k8);
#pragma unroll
    for (int j = 0; j < 4; j++) {
        const float4* pr = pb + (size_t)(u + j * 16) * (JDIM / 4);
        p[j][0] = pr[0];
        p[j][1] = pr[1];
    }

#pragma unroll
    for (int j = 0; j < 4; j++) {
        __half h[8];
        h[0] = __float2half_rn(tanh_hw(e0.x + p[j][0].x));
        h[1] = __float2half_rn(tanh_hw(e0.y + p[j][0].y));
        h[2] = __float2half_rn(tanh_hw(e0.z + p[j][0].z));
        h[3] = __float2half_rn(tanh_hw(e0.w + p[j][0].w));
        h[4] = __float2half_rn(tanh_hw(e1.x + p[j][1].x));
        h[5] = __float2half_rn(tanh_hw(e1.y + p[j][1].y));
        h[6] = __float2half_rn(tanh_hw(e1.z + p[j][1].z));
        h[7] = __float2half_rn(tanh_hw(e1.w + p[j][1].w));
        uint4 H;
        H.x = pack2h(h[0], h[1]); H.y = pack2h(h[2], h[3]);
        H.z = pack2h(h[4], h[5]); H.w = pack2h(h[6], h[7]);
        *(uint4*)(g_a + (size_t)(bt * UU + u + j * 16) * JDIM + k8) = H;
    }
}

// ---------------------------------------------------------------------------
// Joint GEMM via mma.sync (HMMA): C = A_fp16 @ Wt_fp16^T + bias  (single pass)
// BM=128, BN=128, BK=64, 256 threads (8 warps 2x4), warp tile 64x32.
// NPIPE=3 cp.async pipeline, 111.6 KB smem -> 2 blocks/SM. (R10, unchanged.)
// ---------------------------------------------------------------------------
#define BM 128
#define BN 128
#define BK 64
#define NSTG 8                          // 512 / 64
#define NPIPE 3
#define ASTRIDE 144                     // 64 fp16 = 128B data, padded to 144B
#define A_PLANE (BM * ASTRIDE)          // 18432
#define B_PLANE (BN * ASTRIDE)          // 18432
#define STG_BYTES (A_PLANE + B_PLANE)   // 36864
#define OFF_A 0
#define OFF_B A_PLANE
#define JOINT_SMEM (NPIPE * STG_BYTES + 1024)  // 111616 (+bias)

__device__ __forceinline__ void load_stage(uint32_t sbase, int k0, int m0, int n0, int tid) {
#pragma unroll
    for (int it = 0; it < 4; it++) {
        int c = tid + it * 256;            // 0..1023
        int row = c >> 3, cq = c & 7;
        CP16(sbase + OFF_A + row * ASTRIDE + cq * 16,
             g_a + (size_t)(m0 + row) * JDIM + k0 + cq * 8);
    }
#pragma unroll
    for (int it = 0; it < 4; it++) {
        int c = tid + it * 256;            // 0..1023
        int row = c >> 3, cq = c & 7;
        CP16(sbase + OFF_B + row * ASTRIDE + cq * 16,
             g_wt + (size_t)(n0 + row) * JDIM + k0 + cq * 8);
    }
}

__global__ __launch_bounds__(256, 2) void joint_kernel(
    const float* __restrict__ bias, float* __restrict__ out)
{
    extern __shared__ char dsm[];
    const uint32_t sb = smem_u32(dsm);
    float* sbias = (float*)(dsm + NPIPE * STG_BYTES);

    const int tid = threadIdx.x;
    const int l   = tid & 31;
    const int w   = tid >> 5;
    const int mw  = w & 1;        // 0..1  -> 64-row slab
    const int nw  = w >> 1;       // 0..3  -> 32-col slab
    const int bid = blockIdx.x;
    const int n0  = (bid & 7) * BN;     // n-major within m: co-resident N-blocks share A via L2
    const int m0  = (bid >> 3) * BM;

    if (tid < BN) sbias[tid] = bias[n0 + tid];

    load_stage(sb + 0 * STG_BYTES, 0 * BK, m0, n0, tid); CP_COMMIT();
    load_stage(sb + 1 * STG_BYTES, 1 * BK, m0, n0, tid); CP_COMMIT();

    float acc[4][4][4];
#pragma unroll
    for (int i = 0; i < 4; i++)
#pragma unroll
        for (int j = 0; j < 4; j++)
#pragma unroll
            for (int q = 0; q < 4; q++) acc[i][j][q] = 0.0f;

    const uint32_t a_off = (uint32_t)((mw * 64 + (l & 15)) * ASTRIDE + (l >> 4) * 16);
    const uint32_t b_off = (uint32_t)((nw * 32 + ((l >> 4) << 3) + (l & 7)) * ASTRIDE
                                      + ((l >> 3) & 1) * 16);

    for (int s = 0; s < NSTG; s++) {
        asm volatile("cp.async.wait_group 1;" ::: "memory");
        __syncthreads();

        const uint32_t stg = sb + (s % NPIPE) * STG_BYTES;
        uint32_t aa[2][4][4], bb[2][2][4];

        // ---- kk-pair 0 (kk = 0,1) ----
#pragma unroll
        for (int kk = 0; kk < 2; kk++) {
#pragma unroll
            for (int mf = 0; mf < 4; mf++)
                LDSM4(aa[kk][mf], stg + OFF_A + a_off + kk * 32 + mf * 16 * ASTRIDE);
#pragma unroll
            for (int np = 0; np < 2; np++)
                LDSM4(bb[kk][np], stg + OFF_B + b_off + kk * 32 + np * 16 * ASTRIDE);
        }
        // prefetch stage s+2 in the shadow (uniform commit)
        if (s + 2 < NSTG)
            load_stage(sb + ((s + 2) % NPIPE) * STG_BYTES, (s + 2) * BK, m0, n0, tid);
        CP_COMMIT();
#pragma unroll
        for (int kk = 0; kk < 2; kk++)
#pragma unroll
            for (int mf = 0; mf < 4; mf++)
#pragma unroll
                for (int np = 0; np < 2; np++) {
                    MMA16816(acc[mf][np * 2 + 0], aa[kk][mf], bb[kk][np][0], bb[kk][np][1]);
                    MMA16816(acc[mf][np * 2 + 1], aa[kk][mf], bb[kk][np][2], bb[kk][np][3]);
                }

        // ---- kk-pair 1 (kk = 2,3), registers reused ----
#pragma unroll
        for (int kk = 0; kk < 2; kk++) {
#pragma unroll
            for (int mf = 0; mf < 4; mf++)
                LDSM4(aa[kk][mf], stg + OFF_A + a_off + 64 + kk * 32 + mf * 16 * ASTRIDE);
#pragma unroll
            for (int np = 0; np < 2; np++)
                LDSM4(bb[kk][np], stg + OFF_B + b_off + 64 + kk * 32 + np * 16 * ASTRIDE);
        }
#pragma unroll
        for (int kk = 0; kk < 2; kk++)
#pragma unroll
            for (int mf = 0; mf < 4; mf++)
#pragma unroll
                for (int np = 0; np < 2; np++) {
                    MMA16816(acc[mf][np * 2 + 0], aa[kk][mf], bb[kk][np][0], bb[kk][np][1]);
                    MMA16816(acc[mf][np * 2 + 1], aa[kk][mf], bb[kk][np][2], bb[kk][np][3]);
                }
    }

    // epilogue: add bias, direct stores
#pragma unroll
    for (int mf = 0; mf < 4; mf++) {
        const int r0 = m0 + mw * 64 + mf * 16 + (l >> 2);
#pragma unroll
        for (int nf = 0; nf < 4; nf++) {
            const int c  = n0 + nw * 32 + nf * 8 + ((l & 3) << 1);
            const float2 b2 = *(const float2*)&sbias[c - n0];
            float2 o0, o1;
            o0.x = acc[mf][nf][0] + b2.x;
            o0.y = acc[mf][nf][1] + b2.y;
            o1.x = acc[mf][nf][2] + b2.x;
            o1.y = acc[mf][nf][3] + b2.y;
            *(float2*)&out[(size_t)r0 * VOCAB + c]       = o0;
            *(float2*)&out[(size_t)(r0 + 8) * VOCAB + c] = o1;
        }
    }
}

// ---------------------------------------------------------------------------
extern "C" void kernel_launch(void* const* d_in, const int* in_sizes, int n_in,
                              void* d_out, int out_size)
{
    const float* enc_out  = (const float*)d_in[0];
    const float* pred_out = (const float*)d_in[1];
    const float* W_enc    = (const float*)d_in[2];
    const float* b_enc    = (const float*)d_in[3];
    const float* W_pred   = (const float*)d_in[4];
    const float* b_pred   = (const float*)d_in[5];
    const float* W_joint  = (const float*)d_in[6];
    const float* b_joint  = (const float*)d_in[7];
    float* out = (float*)d_out;

    static bool attr_done = false;
    if (!attr_done) {
        cudaFuncSetAttribute(joint_kernel, cudaFuncAttributeMaxDynamicSharedMemorySize, JOINT_SMEM);
        attr_done = true;
    }

    // all three preps in one launch (independent block ranges)
    prep_kernel<<<328, 256>>>(enc_out, W_enc, b_enc, pred_out, W_pred, b_pred, W_joint);
    // tanh(A) fp16 plane
    prep_a_kernel<<<(MROWS / 4) * (JDIM / 8) / 256, 256>>>();
    // joint GEMM: 1024 m-tiles x 8 n-tiles, n-major within m
    joint_kernel<<<(MROWS / BM) * (VOCAB / BN), 256, JOINT_SMEM>>>(b_joint, out);
}

// round 16
// speedup vs baseline: 2.3778x; 1.0854x over previous
#include <cuda_runtime.h>
#include <cuda_fp16.h>
#include <cstdint>

#define BB 8
#define TT 256
#define UU 64
#define ENC_DIM 512
#define PRED_DIM 640
#define JDIM 512
#define VOCAB 1024
#define MROWS (BB * TT * UU)   // 131072

// ---------------------------------------------------------------------------
// Device scratch
// ---------------------------------------------------------------------------
__device__ float g_enc_p[BB * TT * JDIM];               // 4 MB
__device__ float g_pred_p[BB * UU * JDIM];              // 1 MB
__device__ __half g_a[(size_t)MROWS * JDIM];            // 128 MB (fp16 tanh plane)
__device__ __half g_wt[VOCAB * JDIM];                   // 1 MB  (W_joint^T fp16)
__device__ __half g_enc_h[BB * TT * ENC_DIM];           // 2 MB  (enc_out fp16)
__device__ __half g_pred_h[BB * UU * PRED_DIM];         // 0.65 MB
__device__ __half g_wenc_t[JDIM * ENC_DIM];             // [n,k] fp16
__device__ __half g_wpred_t[JDIM * PRED_DIM];           // [n,k] fp16

// ---------------------------------------------------------------------------
// Helpers
// ---------------------------------------------------------------------------
__device__ __forceinline__ uint32_t smem_u32(const void* p) {
    uint32_t a;
    asm("{ .reg .u64 t; cvta.to.shared.u64 t, %1; cvt.u32.u64 %0, t; }" : "=r"(a) : "l"(p));
    return a;
}
#define CP16(dst, src) \
    asm volatile("cp.async.cg.shared.global [%0], [%1], 16;" :: "r"((uint32_t)(dst)), "l"(src) : "memory")
#define CP_COMMIT() asm volatile("cp.async.commit_group;" ::: "memory")

#define LDSM4(r, addr) \
    asm volatile("ldmatrix.sync.aligned.m8n8.x4.shared.b16 {%0,%1,%2,%3}, [%4];" \
                 : "=r"((r)[0]), "=r"((r)[1]), "=r"((r)[2]), "=r"((r)[3]) : "r"(addr))

#define MMA16816(acc, a, b0, b1) \
    asm volatile("mma.sync.aligned.m16n8k16.row.col.f32.f16.f16.f32 " \
                 "{%0,%1,%2,%3},{%4,%5,%6,%7},{%8,%9},{%0,%1,%2,%3};" \
                 : "+f"((acc)[0]), "+f"((acc)[1]), "+f"((acc)[2]), "+f"((acc)[3]) \
                 : "r"((a)[0]), "r"((a)[1]), "r"((a)[2]), "r"((a)[3]), "r"(b0), "r"(b1))

// HW tanh (MUFU.TANH): ~2^-11 accuracy, matches fp16 quantization scale
__device__ __forceinline__ float tanh_hw(float x) {
    float y;
    asm("tanh.approx.f32 %0, %1;" : "=f"(y) : "f"(x));
    return y;
}
__device__ __forceinline__ uint32_t pack2h(__half a, __half b) {
    return (uint32_t)__half_as_ushort(a) | ((uint32_t)__half_as_ushort(b) << 16);
}

// ---------------------------------------------------------------------------
// convert: fp16-quantize inputs and transpose weight matrices.
//   seg1: enc_out -> g_enc_h                 [0, 1048576)
//   seg2: pred_out -> g_pred_h               [.., +327680)
//   seg3: W_enc[k,n] -> g_wenc_t[n,k]        [.., +262144)
//   seg4: W_pred[k,n] -> g_wpred_t[n,k]      [.., +327680)
//   seg5: W_joint[k,v] -> g_wt[v,k]          [.., +524288)
// ---------------------------------------------------------------------------
#define S1 (BB * TT * ENC_DIM)
#define S2 (BB * UU * PRED_DIM)
#define S3 (JDIM * ENC_DIM)
#define S4 (JDIM * PRED_DIM)
#define S5 (VOCAB * JDIM)
#define CONV_TOTAL (S1 + S2 + S3 + S4 + S5)   // 2490368

__global__ __launch_bounds__(256) void convert_kernel(
    const float* __restrict__ enc_out, const float* __restrict__ pred_out,
    const float* __restrict__ W_enc, const float* __restrict__ W_pred,
    const float* __restrict__ W_joint)
{
    int gid = blockIdx.x * 256 + threadIdx.x;
    if (gid < S1) {
        g_enc_h[gid] = __float2half_rn(enc_out[gid]);
    } else if ((gid -= S1) < S2) {
        g_pred_h[gid] = __float2half_rn(pred_out[gid]);
    } else if ((gid -= S2) < S3) {
        int n = gid >> 9, k = gid & 511;
        g_wenc_t[gid] = __float2half_rn(W_enc[k * JDIM + n]);
    } else if ((gid -= S3) < S4) {
        int n = gid / PRED_DIM, k = gid - n * PRED_DIM;
        g_wpred_t[gid] = __float2half_rn(W_pred[k * JDIM + n]);
    } else if ((gid -= S4) < S5) {
        int v = gid >> 9, k = gid & 511;
        g_wt[gid] = __float2half_rn(W_joint[k * VOCAB + v]);
    }
}

// ---------------------------------------------------------------------------
// Shared HMMA tile config (used by proj_hmma and joint)
// ---------------------------------------------------------------------------
#define BM 128
#define BN 128
#define BK 64
#define NPIPE 3
#define ASTRIDE 144                     // 64 fp16 = 128B data, padded to 144B
#define A_PLANE (BM * ASTRIDE)          // 18432
#define B_PLANE (BN * ASTRIDE)          // 18432
#define STG_BYTES (A_PLANE + B_PLANE)   // 36864
#define OFF_A 0
#define OFF_B A_PLANE
#define HMMA_SMEM (NPIPE * STG_BYTES + 1024)  // 111616 (+bias)

__device__ __forceinline__ void load_stage_g(uint32_t sbase,
                                             const __half* __restrict__ A,
                                             const __half* __restrict__ Bt,
                                             int K, int k0, int m0, int n0, int tid) {
#pragma unroll
    for (int it = 0; it < 4; it++) {
        int c = tid + it * 256;
        int row = c >> 3, cq = c & 7;
        CP16(sbase + OFF_A + row * ASTRIDE + cq * 16,
             A + (size_t)(m0 + row) * K + k0 + cq * 8);
    }
#pragma unroll
    for (int it = 0; it < 4; it++) {
        int c = tid + it * 256;
        int row = c >> 3, cq = c & 7;
        CP16(sbase + OFF_B + row * ASTRIDE + cq * 16,
             Bt + (size_t)(n0 + row) * K + k0 + cq * 8);
    }
}

// ---------------------------------------------------------------------------
// HMMA projections: both enc and pred projections in one launch.
//   blocks [0, 64):  enc_p  = enc_h @ wenc_t^T + b_enc   (M=2048, K=512)
//   blocks [64, 80): pred_p = pred_h @ wpred_t^T + b_pred (M=512, K=640)
// fp32 epilogue into g_enc_p / g_pred_p (row stride JDIM).
// ---------------------------------------------------------------------------
__global__ __launch_bounds__(256, 2) void proj_hmma_kernel(
    const float* __restrict__ b_enc, const float* __restrict__ b_pred)
{
    extern __shared__ char dsm[];
    const uint32_t sb = smem_u32(dsm);
    float* sbias = (float*)(dsm + NPIPE * STG_BYTES);

    const int tid = threadIdx.x;
    const int l   = tid & 31;
    const int w   = tid >> 5;
    const int mw  = w & 1;
    const int nw  = w >> 1;
    const int bid = blockIdx.x;

    const __half* A;
    const __half* Bt;
    const float* bias;
    float* C;
    int K, q;
    if (bid < 64) {
        A = g_enc_h;  Bt = g_wenc_t;  bias = b_enc;  C = g_enc_p;
        K = ENC_DIM;  q = bid;
    } else {
        A = g_pred_h; Bt = g_wpred_t; bias = b_pred; C = g_pred_p;
        K = PRED_DIM; q = bid - 64;
    }
    const int m0 = (q >> 2) * BM;
    const int n0 = (q & 3) * BN;
    const int nstg = K / BK;

    if (tid < BN) sbias[tid] = bias[n0 + tid];

    load_stage_g(sb + 0 * STG_BYTES, A, Bt, K, 0 * BK, m0, n0, tid); CP_COMMIT();
    load_stage_g(sb + 1 * STG_BYTES, A, Bt, K, 1 * BK, m0, n0, tid); CP_COMMIT();

    float acc[4][4][4];
#pragma unroll
    for (int i = 0; i < 4; i++)
#pragma unroll
        for (int j = 0; j < 4; j++)
#pragma unroll
            for (int t = 0; t < 4; t++) acc[i][j][t] = 0.0f;

    const uint32_t a_off = (uint32_t)((mw * 64 + (l & 15)) * ASTRIDE + (l >> 4) * 16);
    const uint32_t b_off = (uint32_t)((nw * 32 + ((l >> 4) << 3) + (l & 7)) * ASTRIDE
                                      + ((l >> 3) & 1) * 16);

    for (int s = 0; s < nstg; s++) {
        asm volatile("cp.async.wait_group 1;" ::: "memory");
        __syncthreads();

        const uint32_t stg = sb + (s % NPIPE) * STG_BYTES;
        uint32_t aa[2][4][4], bb[2][2][4];

#pragma unroll
        for (int kk = 0; kk < 2; kk++) {
#pragma unroll
            for (int mf = 0; mf < 4; mf++)
                LDSM4(aa[kk][mf], stg + OFF_A + a_off + kk * 32 + mf * 16 * ASTRIDE);
#pragma unroll
            for (int np = 0; np < 2; np++)
                LDSM4(bb[kk][np], stg + OFF_B + b_off + kk * 32 + np * 16 * ASTRIDE);
        }
        if (s + 2 < nstg)
            load_stage_g(sb + ((s + 2) % NPIPE) * STG_BYTES, A, Bt, K, (s + 2) * BK, m0, n0, tid);
        CP_COMMIT();
#pragma unroll
        for (int kk = 0; kk < 2; kk++)
#pragma unroll
            for (int mf = 0; mf < 4; mf++)
#pragma unroll
                for (int np = 0; np < 2; np++) {
                    MMA16816(acc[mf][np * 2 + 0], aa[kk][mf], bb[kk][np][0], bb[kk][np][1]);
                    MMA16816(acc[mf][np * 2 + 1], aa[kk][mf], bb[kk][np][2], bb[kk][np][3]);
                }

#pragma unroll
        for (int kk = 0; kk < 2; kk++) {
#pragma unroll
            for (int mf = 0; mf < 4; mf++)
                LDSM4(aa[kk][mf], stg + OFF_A + a_off + 64 + kk * 32 + mf * 16 * ASTRIDE);
#pragma unroll
            for (int np = 0; np < 2; np++)
                LDSM4(bb[kk][np], stg + OFF_B + b_off + 64 + kk * 32 + np * 16 * ASTRIDE);
        }
#pragma unroll
        for (int kk = 0; kk < 2; kk++)
#pragma unroll
            for (int mf = 0; mf < 4; mf++)
#pragma unroll
                for (int np = 0; np < 2; np++) {
                    MMA16816(acc[mf][np * 2 + 0], aa[kk][mf], bb[kk][np][0], bb[kk][np][1]);
                    MMA16816(acc[mf][np * 2 + 1], aa[kk][mf], bb[kk][np][2], bb[kk][np][3]);
                }
    }

    // epilogue: add bias, fp32 stores (row stride JDIM)
#pragma unroll
    for (int mf = 0; mf < 4; mf++) {
        const int r0 = m0 + mw * 64 + mf * 16 + (l >> 2);
#pragma unroll
        for (int nf = 0; nf < 4; nf++) {
            const int c  = n0 + nw * 32 + nf * 8 + ((l & 3) << 1);
            const float2 b2 = *(const float2*)&sbias[c - n0];
            float2 o0, o1;
            o0.x = acc[mf][nf][0] + b2.x;
            o0.y = acc[mf][nf][1] + b2.y;
            o1.x = acc[mf][nf][2] + b2.x;
            o1.y = acc[mf][nf][3] + b2.y;
            *(float2*)&C[(size_t)r0 * JDIM + c]       = o0;
            *(float2*)&C[(size_t)(r0 + 8) * JDIM + c] = o1;
        }
    }
}

// ---------------------------------------------------------------------------
// prep_A v3: A[m,k] = fp16(tanh(enc_p[bt,k] + pred_p[b,u,k]))
// Flat mapping, 4 u-rows per thread: 10 independent LDG.128 up front.
// ---------------------------------------------------------------------------
__global__ __launch_bounds__(256) void prep_a_kernel() {
    int gid = blockIdx.x * 256 + threadIdx.x;   // 0 .. 2097151
    int bt = gid >> 10;
    int r  = gid & 1023;
    int u  = r >> 6;                    // 0..15
    int k8 = (r & 63) << 3;
    int b  = bt >> 8;

    const float4* e = (const float4*)(g_enc_p + (size_t)bt * JDIM + k8);
    const float4 e0 = e[0], e1 = e[1];

    float4 p[4][2];
    const float4* pb = (const float4*)(g_pred_p + ((size_t)(b * UU)) * JDIM + k8);
#pragma unroll
    for (int j = 0; j < 4; j++) {
        const float4* pr = pb + (size_t)(u + j * 16) * (JDIM / 4);
        p[j][0] = pr[0];
        p[j][1] = pr[1];
    }

#pragma unroll
    for (int j = 0; j < 4; j++) {
        __half h[8];
        h[0] = __float2half_rn(tanh_hw(e0.x + p[j][0].x));
        h[1] = __float2half_rn(tanh_hw(e0.y + p[j][0].y));
        h[2] = __float2half_rn(tanh_hw(e0.z + p[j][0].z));
        h[3] = __float2half_rn(tanh_hw(e0.w + p[j][0].w));
        h[4] = __float2half_rn(tanh_hw(e1.x + p[j][1].x));
        h[5] = __float2half_rn(tanh_hw(e1.y + p[j][1].y));
        h[6] = __float2half_rn(tanh_hw(e1.z + p[j][1].z));
        h[7] = __float2half_rn(tanh_hw(e1.w + p[j][1].w));
        uint4 H;
        H.x = pack2h(h[0], h[1]); H.y = pack2h(h[2], h[3]);
        H.z = pack2h(h[4], h[5]); H.w = pack2h(h[6], h[7]);
        *(uint4*)(g_a + (size_t)(bt * UU + u + j * 16) * JDIM + k8) = H;
    }
}

// ---------------------------------------------------------------------------
// Joint GEMM via mma.sync (HMMA): C = A_fp16 @ Wt_fp16^T + bias  (single pass)
// BM=128, BN=128, BK=64, 256 threads (8 warps 2x4), warp tile 64x32.
// NPIPE=3 cp.async pipeline, 2 blocks/SM. (R10, unchanged.)
// ---------------------------------------------------------------------------
#define NSTG 8                          // 512 / 64

__global__ __launch_bounds__(256, 2) void joint_kernel(
    const float* __restrict__ bias, float* __restrict__ out)
{
    extern __shared__ char dsm[];
    const uint32_t sb = smem_u32(dsm);
    float* sbias = (float*)(dsm + NPIPE * STG_BYTES);

    const int tid = threadIdx.x;
    const int l   = tid & 31;
    const int w   = tid >> 5;
    const int mw  = w & 1;
    const int nw  = w >> 1;
    const int bid = blockIdx.x;
    const int n0  = (bid & 7) * BN;
    const int m0  = (bid >> 3) * BM;

    if (tid < BN) sbias[tid] = bias[n0 + tid];

    load_stage_g(sb + 0 * STG_BYTES, g_a, g_wt, JDIM, 0 * BK, m0, n0, tid); CP_COMMIT();
    load_stage_g(sb + 1 * STG_BYTES, g_a, g_wt, JDIM, 1 * BK, m0, n0, tid); CP_COMMIT();

    float acc[4][4][4];
#pragma unroll
    for (int i = 0; i < 4; i++)
#pragma unroll
        for (int j = 0; j < 4; j++)
#pragma unroll
            for (int q = 0; q < 4; q++) acc[i][j][q] = 0.0f;

    const uint32_t a_off = (uint32_t)((mw * 64 + (l & 15)) * ASTRIDE + (l >> 4) * 16);
    const uint32_t b_off = (uint32_t)((nw * 32 + ((l >> 4) << 3) + (l & 7)) * ASTRIDE
                                      + ((l >> 3) & 1) * 16);

    for (int s = 0; s < NSTG; s++) {
        asm volatile("cp.async.wait_group 1;" ::: "memory");
        __syncthreads();

        const uint32_t stg = sb + (s % NPIPE) * STG_BYTES;
        uint32_t aa[2][4][4], bb[2][2][4];

#pragma unroll
        for (int kk = 0; kk < 2; kk++) {
#pragma unroll
            for (int mf = 0; mf < 4; mf++)
                LDSM4(aa[kk][mf], stg + OFF_A + a_off + kk * 32 + mf * 16 * ASTRIDE);
#pragma unroll
            for (int np = 0; np < 2; np++)
                LDSM4(bb[kk][np], stg + OFF_B + b_off + kk * 32 + np * 16 * ASTRIDE);
        }
        if (s + 2 < NSTG)
            load_stage_g(sb + ((s + 2) % NPIPE) * STG_BYTES, g_a, g_wt, JDIM, (s + 2) * BK, m0, n0, tid);
        CP_COMMIT();
#pragma unroll
        for (int kk = 0; kk < 2; kk++)
#pragma unroll
            for (int mf = 0; mf < 4; mf++)
#pragma unroll
                for (int np = 0; np < 2; np++) {
                    MMA16816(acc[mf][np * 2 + 0], aa[kk][mf], bb[kk][np][0], bb[kk][np][1]);
                    MMA16816(acc[mf][np * 2 + 1], aa[kk][mf], bb[kk][np][2], bb[kk][np][3]);
                }

#pragma unroll
        for (int kk = 0; kk < 2; kk++) {
#pragma unroll
            for (int mf = 0; mf < 4; mf++)
                LDSM4(aa[kk][mf], stg + OFF_A + a_off + 64 + kk * 32 + mf * 16 * ASTRIDE);
#pragma unroll
            for (int np = 0; np < 2; np++)
                LDSM4(bb[kk][np], stg + OFF_B + b_off + 64 + kk * 32 + np * 16 * ASTRIDE);
        }
#pragma unroll
        for (int kk = 0; kk < 2; kk++)
#pragma unroll
            for (int mf = 0; mf < 4; mf++)
#pragma unroll
                for (int np = 0; np < 2; np++) {
                    MMA16816(acc[mf][np * 2 + 0], aa[kk][mf], bb[kk][np][0], bb[kk][np][1]);
                    MMA16816(acc[mf][np * 2 + 1], aa[kk][mf], bb[kk][np][2], bb[kk][np][3]);
                }
    }

    // epilogue: add bias, direct stores
#pragma unroll
    for (int mf = 0; mf < 4; mf++) {
        const int r0 = m0 + mw * 64 + mf * 16 + (l >> 2);
#pragma unroll
        for (int nf = 0; nf < 4; nf++) {
            const int c  = n0 + nw * 32 + nf * 8 + ((l & 3) << 1);
            const float2 b2 = *(const float2*)&sbias[c - n0];
            float2 o0, o1;
            o0.x = acc[mf][nf][0] + b2.x;
            o0.y = acc[mf][nf][1] + b2.y;
            o1.x = acc[mf][nf][2] + b2.x;
            o1.y = acc[mf][nf][3] + b2.y;
            *(float2*)&out[(size_t)r0 * VOCAB + c]       = o0;
            *(float2*)&out[(size_t)(r0 + 8) * VOCAB + c] = o1;
        }
    }
}

// ---------------------------------------------------------------------------
extern "C" void kernel_launch(void* const* d_in, const int* in_sizes, int n_in,
                              void* d_out, int out_size)
{
    const float* enc_out  = (const float*)d_in[0];
    const float* pred_out = (const float*)d_in[1];
    const float* W_enc    = (const float*)d_in[2];
    const float* b_enc    = (const float*)d_in[3];
    const float* W_pred   = (const float*)d_in[4];
    const float* b_pred   = (const float*)d_in[5];
    const float* W_joint  = (const float*)d_in[6];
    const float* b_joint  = (const float*)d_in[7];
    float* out = (float*)d_out;

    static bool attr_done = false;
    if (!attr_done) {
        cudaFuncSetAttribute(proj_hmma_kernel, cudaFuncAttributeMaxDynamicSharedMemorySize, HMMA_SMEM);
        cudaFuncSetAttribute(joint_kernel, cudaFuncAttributeMaxDynamicSharedMemorySize, HMMA_SMEM);
        attr_done = true;
    }

    // 1) fp16 conversions + weight transposes
    convert_kernel<<<(CONV_TOTAL + 255) / 256, 256>>>(enc_out, pred_out, W_enc, W_pred, W_joint);
    // 2) both projections on tensor cores
    proj_hmma_kernel<<<80, 256, HMMA_SMEM>>>(b_enc, b_pred);
    // 3) tanh(A) fp16 plane
    prep_a_kernel<<<(MROWS / 4) * (JDIM / 8) / 256, 256>>>();
    // 4) joint GEMM: 1024 m-tiles x 8 n-tiles, n-major within m
    joint_kernel<<<(MROWS / BM) * (VOCAB / BN), 256, HMMA_SMEM>>>(b_joint, out);
}